// round 6
// baseline (speedup 1.0000x reference)
#include <cuda_runtime.h>
#include <math.h>

#define HW 24
#define NPOS 576
#define XZQ 442368            // one K-quarter of xz: 2n * 384 * 576

// Scratch (__device__ globals: allocation-free rule)
__device__ float g_xz[4 * XZQ];          // [kq][n][384][576]
__device__ float g_mid[2 * 96 * NPOS];
__device__ float g_wT[2 * 864 * 384];
__device__ float g_rs0[2 * 96 * 24];     // layer-0 rms row scales
__device__ float g_rs1[2 * 96 * 24];     // layer-1 rms row scales

typedef unsigned long long ull;

__device__ __forceinline__ void ffma2(ull& acc, ull a, ull b) {
    asm("fma.rn.f32x2 %0, %1, %2, %0;" : "+l"(acc) : "l"(a), "l"(b));
}
__device__ __forceinline__ ull dup2(float v) {
    ull r;
    asm("mov.b64 %0, {%1, %1};" : "=l"(r) : "f"(v));
    return r;
}
__device__ __forceinline__ float2 up(ull a) { return *(float2*)&a; }

// ---------- weight transpose: [co][ci*9+t] -> [ci*9+t][co] ----------
__global__ void wt_kernel(const float* __restrict__ ipw) {
    __shared__ float tile[32][33];
    int r0 = blockIdx.x * 32, c0 = blockIdx.y * 32, l = blockIdx.z;
    int tx = threadIdx.x, ty = threadIdx.y;   // (32, 8)
    const float* src = ipw + (size_t)l * 331776;
    float* dst = g_wT + (size_t)l * 331776;
    #pragma unroll
    for (int i = 0; i < 4; i++)
        tile[ty + 8 * i][tx] = src[(size_t)(c0 + ty + 8 * i) * 864 + r0 + tx];
    __syncthreads();
    #pragma unroll
    for (int i = 0; i < 4; i++)
        dst[(size_t)(r0 + ty + 8 * i) * 384 + c0 + tx] = tile[tx][ty + 8 * i];
}

// ---------- layer-0 rms row scales (no rewrite) ----------
__global__ void rs0_kernel(const float* __restrict__ src, long cs, long ns,
                           const float* __restrict__ nw) {
    int row = blockIdx.x * 128 + threadIdx.x;
    if (row >= 2 * 96 * 24) return;
    int h = row % 24;
    int c = (row / 24) % 96;
    int n = row / (24 * 96);
    const float* p = src + (size_t)n * ns + (size_t)c * cs + h * 24;
    float s = 0.f;
    #pragma unroll
    for (int j = 0; j < 6; j++) {
        float4 v = *(const float4*)(p + 4 * j);
        s += v.x * v.x + v.y * v.y + v.z * v.z + v.w * v.w;
    }
    g_rs0[(n * 96 + c) * 24 + h] = rsqrtf(s * (1.f / 24.f) + 1e-5f) * __ldg(nw + c);
}

// ---------- 3x3 conv (96 -> 384), scale applied at staging, K-split by 4 ----------
// block: 64 co x (4h x 24w), 24-ci quarter; 192 threads, 2 CTAs/SM
// grid: (6 htile, 6 ctile, 8 = n*4 + kq)
// thread tile: 4 co (2 f32x2 co-pairs) x 2 h x 4 w   (w0 16B-aligned)
__global__ void __launch_bounds__(192, 2)
conv_kernel(const float* __restrict__ wT,
            const float* __restrict__ src, long cs, long ns,
            const float* __restrict__ rs,
            float* __restrict__ outp) {
    extern __shared__ float sm[];
    float2* S2 = (float2*)sm;          // [144][28] float2, values duplicated
    float*  W  = sm + 144 * 56;        // [216][68]

    int h0  = blockIdx.x * 4;
    int ct  = blockIdx.y;
    int n   = blockIdx.z >> 2;
    int kq  = blockIdx.z & 3;
    int ci0 = kq * 24;
    int tid = threadIdx.x;

    // stage normalized input (24 ci, 6 h rows with halo), duplicated float2
    const float* sb = src + (size_t)n * ns + (size_t)ci0 * cs;
    const float* rb = rs + (n * 96 + ci0) * 24;
    for (int idx = tid; idx < 24 * 6 * 24; idx += 192) {
        int w = idx % 24;
        int row = idx / 24;            // ci*6 + hr
        int hr = row % 6, ci = row / 6;
        int hh = h0 + hr - 1;
        float v = 0.f;
        if (hh >= 0 && hh < 24)
            v = sb[(size_t)ci * cs + hh * 24 + w] * __ldg(rb + ci * 24 + hh);
        S2[row * 28 + 1 + w] = make_float2(v, v);
    }
    if (tid < 144) {
        float2 z = make_float2(0.f, 0.f);
        S2[tid * 28] = z; S2[tid * 28 + 25] = z;
        S2[tid * 28 + 26] = z; S2[tid * 28 + 27] = z;
    }
    // stage weights: rows [ci0*9, +216), cols [ct*64, +64)
    {
        const float* wsrc = wT + (size_t)(ci0 * 9) * 384 + ct * 64;
        for (int idx = tid; idx < 216 * 16; idx += 192) {
            int r = idx >> 4, fq = idx & 15;
            *(float4*)(W + r * 68 + fq * 4) = *(const float4*)(wsrc + (size_t)r * 384 + fq * 4);
        }
    }
    __syncthreads();

    // compute
    int cog  = tid & 15;               // co_local = cog*4
    int posg = tid >> 4;               // 0..11
    int hl   = (posg / 6) * 2;         // 0 or 2
    int w0   = (posg % 6) * 4;         // 0,4,...,20  (16B-aligned in f2 units)

    ull acc[2][2][4];
    #pragma unroll
    for (int a = 0; a < 2; a++)
        #pragma unroll
        for (int dh = 0; dh < 2; dh++)
            #pragma unroll
            for (int dw = 0; dw < 4; dw++) acc[a][dh][dw] = 0ull;

    const float2* Sbase = S2 + hl * 28 + w0;
    const float*  Wbase = W + cog * 4;

    #pragma unroll 1
    for (int ci = 0; ci < 24; ci++) {
        const float2* Sr = Sbase + ci * 168;
        ull ind[4][6];
        #pragma unroll
        for (int r = 0; r < 4; r++) {
            const float4* rp = (const float4*)(Sr + r * 28);
            float4 t0 = rp[0], t1 = rp[1], t2 = rp[2];
            ind[r][0] = *(ull*)&t0.x; ind[r][1] = *(ull*)&t0.z;
            ind[r][2] = *(ull*)&t1.x; ind[r][3] = *(ull*)&t1.z;
            ind[r][4] = *(ull*)&t2.x; ind[r][5] = *(ull*)&t2.z;
        }

        const float* Wr = Wbase + ci * 9 * 68;
        #pragma unroll
        for (int kh = 0; kh < 3; kh++) {
            #pragma unroll
            for (int kw = 0; kw < 3; kw++) {
                const float4 wv = *(const float4*)(Wr + (kh * 3 + kw) * 68);
                ull w01 = *(const ull*)&wv.x;
                ull w23 = *(const ull*)&wv.z;
                #pragma unroll
                for (int dh = 0; dh < 2; dh++) {
                    #pragma unroll
                    for (int dw = 0; dw < 4; dw++) {
                        ffma2(acc[0][dh][dw], w01, ind[dh + kh][dw + kw]);
                        ffma2(acc[1][dh][dw], w23, ind[dh + kh][dw + kw]);
                    }
                }
            }
        }
    }

    int cobase = ct * 64 + cog * 4;
    float* ob = outp + (size_t)kq * XZQ
              + ((size_t)(n * 384 + cobase)) * NPOS + (h0 + hl) * 24 + w0;
    // repack: 4 consecutive w per co -> STG.128
    #pragma unroll
    for (int a = 0; a < 2; a++) {
        #pragma unroll
        for (int dh = 0; dh < 2; dh++) {
            float2 v0 = up(acc[a][dh][0]), v1 = up(acc[a][dh][1]);
            float2 v2 = up(acc[a][dh][2]), v3 = up(acc[a][dh][3]);
            float4 lo = make_float4(v0.x, v1.x, v2.x, v3.x);
            float4 hi = make_float4(v0.y, v1.y, v2.y, v3.y);
            *(float4*)(ob + (size_t)(2 * a) * NPOS + dh * 24)     = lo;
            *(float4*)(ob + (size_t)(2 * a + 1) * NPOS + dh * 24) = hi;
        }
    }
}

// ---------- fused pointwise chain + GEMVs over one (n,h) row (24 pos) ----------
// 192 threads, grid (24 h, 2 n).  Optionally emits next layer's rms scales.
#define XIS 26
__global__ void __launch_bounds__(192, 1)
fused_kernel(const float* __restrict__ cw,  const float* __restrict__ cb,
             const float* __restrict__ xpw, const float* __restrict__ dtw,
             const float* __restrict__ dtb, const float* __restrict__ Dp,
             const float* __restrict__ opw,
             const float* __restrict__ resid, long cs, long ns,
             float* __restrict__ dst,
             const float* __restrict__ nw_next, float* __restrict__ rs_out,
             int do_rs) {
    extern __shared__ float sm[];
    float* xi_s  = sm;                    // [192][26]
    float* dbc_s = sm + 192 * XIS;        // [38][26]
    float* bc_s  = dbc_s + 38 * 26;       // [24]
    float* xpw_s = bc_s + 24;             // [38][196]
    float* opw_s = xpw_s + 38 * 196;      // [96][196]

    int tid = threadIdx.x;
    int hrow = blockIdx.x;
    int n  = blockIdx.y;
    int p0 = hrow * 24;

    for (int t = tid; t < 38 * 48; t += 192) {
        int r = t / 48, q = t % 48;
        *(float4*)(xpw_s + r * 196 + q * 4) = *(const float4*)(xpw + (size_t)r * 192 + q * 4);
    }
    for (int t = tid; t < 96 * 48; t += 192) {
        int r = t / 48, q = t % 48;
        *(float4*)(opw_s + r * 196 + q * 4) = *(const float4*)(opw + (size_t)r * 192 + q * 4);
    }

    // xi = silu(conv1d depth-0 tap + bias); sum the four K-quarters. thread=channel
    const float* xzb = g_xz + (size_t)n * 384 * NPOS + p0;
    {
        int c = tid;
        const float* xrow = xzb + (size_t)c * NPOS;
        float4 a[6];
        #pragma unroll
        for (int j = 0; j < 6; j++) a[j] = *(const float4*)(xrow + 4 * j);
        #pragma unroll
        for (int q = 1; q < 4; q++) {
            const float* xq = xrow + (size_t)q * XZQ;
            #pragma unroll
            for (int j = 0; j < 6; j++) {
                float4 t = *(const float4*)(xq + 4 * j);
                a[j].x += t.x; a[j].y += t.y; a[j].z += t.z; a[j].w += t.w;
            }
        }
        float tap = __ldg(cw + c * 4 + 3), bias = __ldg(cb + c);
        float* xo = xi_s + c * XIS;
        #pragma unroll
        for (int j = 0; j < 6; j++) {
            float e[4] = {a[j].x, a[j].y, a[j].z, a[j].w};
            #pragma unroll
            for (int u = 0; u < 4; u++) {
                float pre = tap * e[u] + bias;
                xo[4 * j + u] = pre / (1.f + __expf(-pre));
            }
        }
    }
    __syncthreads();

    // dbc[38][24] = x_proj @ xi  (3 f32x2 chains per thread)
    {
        int pp = tid & 3;
        int jg = tid >> 2;                // 0..47
        if (jg < 38) {
            ull a0 = 0ull, a1 = 0ull, a2 = 0ull;
            const float* wr = xpw_s + jg * 196;
            const float* xr = xi_s + pp * 6;
            #pragma unroll 4
            for (int c = 0; c < 192; c++) {
                ull wv = dup2(wr[c]);
                const float* xc = xr + c * XIS;
                ffma2(a0, wv, *(const ull*)(xc));
                ffma2(a1, wv, *(const ull*)(xc + 2));
                ffma2(a2, wv, *(const ull*)(xc + 4));
            }
            float* dq = dbc_s + jg * 26 + pp * 6;
            *(ull*)(dq)     = a0;
            *(ull*)(dq + 2) = a1;
            *(ull*)(dq + 4) = a2;
        }
    }
    __syncthreads();

    // bc[p] = B . C
    if (tid < 24) {
        float s = 0.f;
        #pragma unroll
        for (int qq = 0; qq < 16; qq++)
            s += dbc_s[(6 + qq) * 26 + tid] * dbc_s[(22 + qq) * 26 + tid];
        bc_s[tid] = s;
    }
    __syncthreads();

    // delta -> y -> gate; overwrite xi_s with g.  thread=channel
    {
        int c = tid;
        float dw[6];
        #pragma unroll
        for (int r = 0; r < 6; r++) dw[r] = __ldg(dtw + c * 6 + r);
        float bconst = __ldg(dtb + c);
        float Dc = __ldg(Dp + c);
        const float* zrow = xzb + (size_t)(192 + c) * NPOS;
        float z[24];
        #pragma unroll
        for (int j = 0; j < 6; j++) {
            float4 a = *(const float4*)(zrow + 4 * j);
            #pragma unroll
            for (int q = 1; q < 4; q++) {
                float4 t = *(const float4*)(zrow + (size_t)q * XZQ + 4 * j);
                a.x += t.x; a.y += t.y; a.z += t.z; a.w += t.w;
            }
            z[4 * j] = a.x; z[4 * j + 1] = a.y; z[4 * j + 2] = a.z; z[4 * j + 3] = a.w;
        }
        float* xo = xi_s + c * XIS;
        #pragma unroll
        for (int p = 0; p < 24; p++) {
            float d = bconst;
            #pragma unroll
            for (int r = 0; r < 6; r++) d += dw[r] * dbc_s[r * 26 + p];
            float sp = fmaxf(d, 0.f) + log1pf(__expf(-fabsf(d)));
            float zv = z[p];
            xo[p] = xo[p] * (sp * bc_s[p] + Dc) * (zv / (1.f + __expf(-zv)));
        }
    }
    __syncthreads();

    // out = out_proj @ g + residual; optional next-layer rms scale
    {
        int pp = tid & 3;
        int kg = tid >> 2;                // 0..47 -> k = kg*2 + {0,1}
        ull a[2][3];
        #pragma unroll
        for (int i = 0; i < 2; i++)
            #pragma unroll
            for (int j = 0; j < 3; j++) a[i][j] = 0ull;
        const float* xr = xi_s + pp * 6;
        const float* w0p = opw_s + (kg * 2) * 196;
        const float* w1p = w0p + 196;
        #pragma unroll 4
        for (int c = 0; c < 192; c++) {
            ull W0 = dup2(w0p[c]);
            ull W1 = dup2(w1p[c]);
            const float* xc = xr + c * XIS;
            ull g0 = *(const ull*)(xc);
            ull g1 = *(const ull*)(xc + 2);
            ull g2 = *(const ull*)(xc + 4);
            ffma2(a[0][0], W0, g0); ffma2(a[0][1], W0, g1); ffma2(a[0][2], W0, g2);
            ffma2(a[1][0], W1, g0); ffma2(a[1][1], W1, g1); ffma2(a[1][2], W1, g2);
        }
        #pragma unroll
        for (int i = 0; i < 2; i++) {
            int k = kg * 2 + i;
            const float* rb = resid + (size_t)n * ns + (size_t)k * cs + p0 + pp * 6;
            float* db = dst + (size_t)(n * 96 + k) * NPOS + p0 + pp * 6;
            float ss = 0.f;
            #pragma unroll
            for (int j = 0; j < 3; j++) {
                float2 v = up(a[i][j]);
                v.x += rb[2 * j];
                v.y += rb[2 * j + 1];
                *(float2*)(db + 2 * j) = v;
                ss += v.x * v.x + v.y * v.y;
            }
            if (do_rs) {
                ss += __shfl_xor_sync(0xffffffffu, ss, 1);
                ss += __shfl_xor_sync(0xffffffffu, ss, 2);
                if (pp == 0)
                    rs_out[(n * 96 + k) * 24 + hrow] =
                        rsqrtf(ss * (1.f / 24.f) + 1e-5f) * __ldg(nw_next + k);
            }
        }
    }
}

extern "C" void kernel_launch(void* const* d_in, const int* in_sizes, int n_in,
                              void* d_out, int out_size) {
    const float* x          = (const float*)d_in[0];
    const float* in_proj_w  = (const float*)d_in[1];
    const float* conv1d_w   = (const float*)d_in[2];
    const float* conv1d_b   = (const float*)d_in[3];
    const float* x_proj_w   = (const float*)d_in[4];
    const float* dt_proj_w  = (const float*)d_in[5];
    const float* dt_proj_b  = (const float*)d_in[6];
    // d_in[7] = A_log : unused (hs at depth 0 == BX at depth 0)
    const float* Dp         = (const float*)d_in[8];
    const float* out_proj_w = (const float*)d_in[9];
    const float* norm_w     = (const float*)d_in[10];
    float* out = (float*)d_out;

    float *xz = nullptr, *mid = nullptr, *wT = nullptr, *rs0 = nullptr, *rs1 = nullptr;
    cudaGetSymbolAddress((void**)&xz, g_xz);
    cudaGetSymbolAddress((void**)&mid, g_mid);
    cudaGetSymbolAddress((void**)&wT, g_wT);
    cudaGetSymbolAddress((void**)&rs0, g_rs0);
    cudaGetSymbolAddress((void**)&rs1, g_rs1);

    const int CONV_SMEM  = (144 * 56 + 216 * 68) * 4;                        // 91008
    const int FUSED_SMEM = (192 * XIS + 38 * 26 + 24 + 38 * 196 + 96 * 196) * 4;
    cudaFuncSetAttribute(conv_kernel,  cudaFuncAttributeMaxDynamicSharedMemorySize, CONV_SMEM);
    cudaFuncSetAttribute(fused_kernel, cudaFuncAttributeMaxDynamicSharedMemorySize, FUSED_SMEM);

    wt_kernel<<<dim3(27, 12, 2), dim3(32, 8)>>>(in_proj_w);

    // layer 0: input = x depth-0 slice (strided view)
    {
        long cs = 8L * NPOS, ns = 96L * 8L * NPOS;
        rs0_kernel<<<36, 128>>>(x, cs, ns, norm_w);
        conv_kernel<<<dim3(6, 6, 8), 192, CONV_SMEM>>>(wT, x, cs, ns, rs0, xz);
        fused_kernel<<<dim3(24, 2), 192, FUSED_SMEM>>>(
            conv1d_w, conv1d_b, x_proj_w, dt_proj_w, dt_proj_b, Dp, out_proj_w,
            x, cs, ns, mid, norm_w + 96, rs1, 1);
    }
    // layer 1: input = mid (contiguous)
    {
        long cs = (long)NPOS, ns = 96L * NPOS;
        conv_kernel<<<dim3(6, 6, 8), 192, CONV_SMEM>>>(
            wT + 331776, mid, cs, ns, rs1, xz);
        fused_kernel<<<dim3(24, 2), 192, FUSED_SMEM>>>(
            conv1d_w + 768, conv1d_b + 192, x_proj_w + 7296, dt_proj_w + 1152,
            dt_proj_b + 192, Dp + 192, out_proj_w + 18432,
            mid, cs, ns, out, norm_w, rs1, 0);
    }
}

// round 7
// speedup vs baseline: 1.6590x; 1.6590x over previous
#include <cuda_runtime.h>
#include <math.h>

#define HW 24
#define NPOS 576
#define XZQ 442368            // one K-quarter of xz: 2n * 384 * 576

// Scratch (__device__ globals: allocation-free rule)
__device__ float g_xz[4 * XZQ];          // [kq][n][384][576]
__device__ float g_mid[2 * 96 * NPOS];
__device__ float g_wT[2 * 864 * 384];
__device__ float g_rs0[2 * 96 * 24];     // layer-0 rms row scales
__device__ float g_rs1[2 * 96 * 24];     // layer-1 rms row scales

typedef unsigned long long ull;

__device__ __forceinline__ void ffma2(ull& acc, ull a, ull b) {
    asm("fma.rn.f32x2 %0, %1, %2, %0;" : "+l"(acc) : "l"(a), "l"(b));
}
__device__ __forceinline__ ull dup2(float v) {
    ull r;
    asm("mov.b64 %0, {%1, %1};" : "=l"(r) : "f"(v));
    return r;
}
__device__ __forceinline__ float2 up(ull a) { return *(float2*)&a; }

// ---------- weight transpose: [co][ci*9+t] -> [ci*9+t][co] ----------
__global__ void wt_kernel(const float* __restrict__ ipw) {
    __shared__ float tile[32][33];
    int r0 = blockIdx.x * 32, c0 = blockIdx.y * 32, l = blockIdx.z;
    int tx = threadIdx.x, ty = threadIdx.y;   // (32, 8)
    const float* src = ipw + (size_t)l * 331776;
    float* dst = g_wT + (size_t)l * 331776;
    #pragma unroll
    for (int i = 0; i < 4; i++)
        tile[ty + 8 * i][tx] = src[(size_t)(c0 + ty + 8 * i) * 864 + r0 + tx];
    __syncthreads();
    #pragma unroll
    for (int i = 0; i < 4; i++)
        dst[(size_t)(r0 + ty + 8 * i) * 384 + c0 + tx] = tile[tx][ty + 8 * i];
}

// ---------- rms row scales (no data rewrite) ----------
__global__ void rs_kernel(const float* __restrict__ src, long cs, long ns,
                          const float* __restrict__ nw, float* __restrict__ rs) {
    int row = blockIdx.x * 128 + threadIdx.x;
    if (row >= 2 * 96 * 24) return;
    int h = row % 24;
    int c = (row / 24) % 96;
    int n = row / (24 * 96);
    const float* p = src + (size_t)n * ns + (size_t)c * cs + h * 24;
    float s = 0.f;
    #pragma unroll
    for (int j = 0; j < 6; j++) {
        float4 v = *(const float4*)(p + 4 * j);
        s += v.x * v.x + v.y * v.y + v.z * v.z + v.w * v.w;
    }
    rs[(n * 96 + c) * 24 + h] = rsqrtf(s * (1.f / 24.f) + 1e-5f) * __ldg(nw + c);
}

// ---------- 3x3 conv (96 -> 384), scale applied at staging, K-split by 4 ----------
// block: 64 co x (4h x 24w), 24-ci quarter; 192 threads, 2 CTAs/SM
// grid: (6 htile, 6 ctile, 8 = n*4 + kq)
// thread tile: 4 co (2 f32x2 co-pairs) x 2 h x 4 w   (w0 16B-aligned)
__global__ void __launch_bounds__(192, 2)
conv_kernel(const float* __restrict__ wT,
            const float* __restrict__ src, long cs, long ns,
            const float* __restrict__ rs,
            float* __restrict__ outp) {
    extern __shared__ float sm[];
    float2* S2 = (float2*)sm;          // [144][28] float2, values duplicated
    float*  W  = sm + 144 * 56;        // [216][68]

    int h0  = blockIdx.x * 4;
    int ct  = blockIdx.y;
    int n   = blockIdx.z >> 2;
    int kq  = blockIdx.z & 3;
    int ci0 = kq * 24;
    int tid = threadIdx.x;

    // stage normalized input (24 ci, 6 h rows with halo), duplicated float2
    const float* sb = src + (size_t)n * ns + (size_t)ci0 * cs;
    const float* rb = rs + (n * 96 + ci0) * 24;
    for (int idx = tid; idx < 24 * 6 * 24; idx += 192) {
        int w = idx % 24;
        int row = idx / 24;            // ci*6 + hr
        int hr = row % 6, ci = row / 6;
        int hh = h0 + hr - 1;
        float v = 0.f;
        if (hh >= 0 && hh < 24)
            v = sb[(size_t)ci * cs + hh * 24 + w] * __ldg(rb + ci * 24 + hh);
        S2[row * 28 + 1 + w] = make_float2(v, v);
    }
    if (tid < 144) {
        float2 z = make_float2(0.f, 0.f);
        S2[tid * 28] = z; S2[tid * 28 + 25] = z;
        S2[tid * 28 + 26] = z; S2[tid * 28 + 27] = z;
    }
    // stage weights: rows [ci0*9, +216), cols [ct*64, +64)
    {
        const float* wsrc = wT + (size_t)(ci0 * 9) * 384 + ct * 64;
        for (int idx = tid; idx < 216 * 16; idx += 192) {
            int r = idx >> 4, fq = idx & 15;
            *(float4*)(W + r * 68 + fq * 4) = *(const float4*)(wsrc + (size_t)r * 384 + fq * 4);
        }
    }
    __syncthreads();

    // compute
    int cog  = tid & 15;               // co_local = cog*4
    int posg = tid >> 4;               // 0..11
    int hl   = (posg / 6) * 2;         // 0 or 2
    int w0   = (posg % 6) * 4;         // 0,4,...,20  (16B-aligned in f2 units)

    ull acc[2][2][4];
    #pragma unroll
    for (int a = 0; a < 2; a++)
        #pragma unroll
        for (int dh = 0; dh < 2; dh++)
            #pragma unroll
            for (int dw = 0; dw < 4; dw++) acc[a][dh][dw] = 0ull;

    const float2* Sbase = S2 + hl * 28 + w0;
    const float*  Wbase = W + cog * 4;

    #pragma unroll 1
    for (int ci = 0; ci < 24; ci++) {
        const float2* Sr = Sbase + ci * 168;
        ull ind[4][6];
        #pragma unroll
        for (int r = 0; r < 4; r++) {
            const float4* rp = (const float4*)(Sr + r * 28);
            float4 t0 = rp[0], t1 = rp[1], t2 = rp[2];
            ind[r][0] = *(ull*)&t0.x; ind[r][1] = *(ull*)&t0.z;
            ind[r][2] = *(ull*)&t1.x; ind[r][3] = *(ull*)&t1.z;
            ind[r][4] = *(ull*)&t2.x; ind[r][5] = *(ull*)&t2.z;
        }

        const float* Wr = Wbase + ci * 9 * 68;
        #pragma unroll
        for (int kh = 0; kh < 3; kh++) {
            #pragma unroll
            for (int kw = 0; kw < 3; kw++) {
                const float4 wv = *(const float4*)(Wr + (kh * 3 + kw) * 68);
                ull w01 = *(const ull*)&wv.x;
                ull w23 = *(const ull*)&wv.z;
                #pragma unroll
                for (int dh = 0; dh < 2; dh++) {
                    #pragma unroll
                    for (int dw = 0; dw < 4; dw++) {
                        ffma2(acc[0][dh][dw], w01, ind[dh + kh][dw + kw]);
                        ffma2(acc[1][dh][dw], w23, ind[dh + kh][dw + kw]);
                    }
                }
            }
        }
    }

    int cobase = ct * 64 + cog * 4;
    float* ob = outp + (size_t)kq * XZQ
              + ((size_t)(n * 384 + cobase)) * NPOS + (h0 + hl) * 24 + w0;
    // repack: 4 consecutive w per co -> STG.128
    #pragma unroll
    for (int a = 0; a < 2; a++) {
        #pragma unroll
        for (int dh = 0; dh < 2; dh++) {
            float2 v0 = up(acc[a][dh][0]), v1 = up(acc[a][dh][1]);
            float2 v2 = up(acc[a][dh][2]), v3 = up(acc[a][dh][3]);
            float4 lo = make_float4(v0.x, v1.x, v2.x, v3.x);
            float4 hi = make_float4(v0.y, v1.y, v2.y, v3.y);
            *(float4*)(ob + (size_t)(2 * a) * NPOS + dh * 24)     = lo;
            *(float4*)(ob + (size_t)(2 * a + 1) * NPOS + dh * 24) = hi;
        }
    }
}

// ---------- fused pointwise chain + GEMVs over 8-position tiles ----------
// 192 threads, grid (72 ptiles, 2 n)   [R4 version: one full wave]
__global__ void __launch_bounds__(192, 1)
fused_kernel(const float* __restrict__ cw,  const float* __restrict__ cb,
             const float* __restrict__ xpw, const float* __restrict__ dtw,
             const float* __restrict__ dtb, const float* __restrict__ Dp,
             const float* __restrict__ opw,
             const float* __restrict__ resid, long cs, long ns,
             float* __restrict__ dst) {
    extern __shared__ float sm[];
    float* xi_s  = sm;                    // [192][8]
    float* dbc_s = sm + 1536;             // [38][8]
    float* bc_s  = sm + 1840;             // [8]
    float* xpw_s = sm + 1848;             // [38][196]
    float* opw_s = sm + 1848 + 7448;      // [96][196]

    int tid = threadIdx.x;
    int p0 = blockIdx.x * 8;
    int n  = blockIdx.y;

    for (int t = tid; t < 38 * 48; t += 192) {
        int r = t / 48, q = t % 48;
        *(float4*)(xpw_s + r * 196 + q * 4) = *(const float4*)(xpw + (size_t)r * 192 + q * 4);
    }
    for (int t = tid; t < 96 * 48; t += 192) {
        int r = t / 48, q = t % 48;
        *(float4*)(opw_s + r * 196 + q * 4) = *(const float4*)(opw + (size_t)r * 192 + q * 4);
    }

    // xi = silu(conv1d depth-0 tap + bias); sum the four K-quarters
    const float* xzb = g_xz + (size_t)n * 384 * NPOS + p0;
    for (int idx = tid; idx < 1536; idx += 192) {
        int c = idx >> 3, p = idx & 7;
        size_t o = (size_t)c * NPOS + p;
        float v = xzb[o] + xzb[XZQ + o] + xzb[2 * XZQ + o] + xzb[3 * XZQ + o];
        float pre = __ldg(cw + c * 4 + 3) * v + __ldg(cb + c);
        xi_s[idx] = pre / (1.f + __expf(-pre));
    }
    __syncthreads();

    // dbc[38][8] = x_proj @ xi  (two independent chains per thread)
    {
        int pp = tid & 3;
        int jg = tid >> 2;                // 0..47
        if (jg < 38) {
            ull a0 = 0ull, a1 = 0ull;
            const float* wr = xpw_s + jg * 196;
            const float* xr = xi_s + pp * 2;
            #pragma unroll 4
            for (int c = 0; c < 96; c++) {
                ffma2(a0, dup2(wr[c]),      *(const ull*)(xr + c * 8));
                ffma2(a1, dup2(wr[96 + c]), *(const ull*)(xr + (96 + c) * 8));
            }
            float2 v0 = up(a0), v1 = up(a1);
            float2 r = make_float2(v0.x + v1.x, v0.y + v1.y);
            *(float2*)(dbc_s + jg * 8 + pp * 2) = r;
        }
    }
    __syncthreads();

    // bc[p] = B . C
    if (tid < 8) {
        float s = 0.f;
        #pragma unroll
        for (int qq = 0; qq < 16; qq++)
            s += dbc_s[(6 + qq) * 8 + tid] * dbc_s[(22 + qq) * 8 + tid];
        bc_s[tid] = s;
    }
    __syncthreads();

    // delta -> y -> gate; overwrite xi_s with g
    {
        int c = tid;
        float dw[6];
        #pragma unroll
        for (int r = 0; r < 6; r++) dw[r] = __ldg(dtw + c * 6 + r);
        float bconst = __ldg(dtb + c);
        float Dc = __ldg(Dp + c);
        const float* zrow = xzb + (size_t)(192 + c) * NPOS;
        #pragma unroll
        for (int p = 0; p < 8; p++) {
            float d = bconst;
            #pragma unroll
            for (int r = 0; r < 6; r++) d += dw[r] * dbc_s[r * 8 + p];
            float sp = fmaxf(d, 0.f) + log1pf(__expf(-fabsf(d)));
            float z = zrow[p] + zrow[XZQ + p] + zrow[2 * XZQ + p] + zrow[3 * XZQ + p];
            float g = xi_s[c * 8 + p] * (sp * bc_s[p] + Dc) * (z / (1.f + __expf(-z)));
            xi_s[c * 8 + p] = g;
        }
    }
    __syncthreads();

    // out = out_proj @ g + residual  (4 independent chains per thread)
    {
        int pp = tid & 3;
        int kg = tid >> 2;                // 0..47 -> 2 k each
        ull a[2][2] = {{0ull, 0ull}, {0ull, 0ull}};
        const float* xr = xi_s + pp * 2;
        #pragma unroll 4
        for (int c = 0; c < 96; c++) {
            ull g0 = *(const ull*)(xr + c * 8);
            ull g1 = *(const ull*)(xr + (96 + c) * 8);
            #pragma unroll
            for (int i = 0; i < 2; i++) {
                ffma2(a[i][0], dup2(opw_s[(kg * 2 + i) * 196 + c]),      g0);
                ffma2(a[i][1], dup2(opw_s[(kg * 2 + i) * 196 + 96 + c]), g1);
            }
        }
        #pragma unroll
        for (int i = 0; i < 2; i++) {
            int k = kg * 2 + i;
            float2 v0 = up(a[i][0]), v1 = up(a[i][1]);
            float2 v = make_float2(v0.x + v1.x, v0.y + v1.y);
            const float* rb = resid + (size_t)n * ns + (size_t)k * cs + p0 + pp * 2;
            v.x += rb[0];
            v.y += rb[1];
            *(float2*)(dst + (size_t)(n * 96 + k) * NPOS + p0 + pp * 2) = v;
        }
    }
}

extern "C" void kernel_launch(void* const* d_in, const int* in_sizes, int n_in,
                              void* d_out, int out_size) {
    const float* x          = (const float*)d_in[0];
    const float* in_proj_w  = (const float*)d_in[1];
    const float* conv1d_w   = (const float*)d_in[2];
    const float* conv1d_b   = (const float*)d_in[3];
    const float* x_proj_w   = (const float*)d_in[4];
    const float* dt_proj_w  = (const float*)d_in[5];
    const float* dt_proj_b  = (const float*)d_in[6];
    // d_in[7] = A_log : unused (hs at depth 0 == BX at depth 0)
    const float* Dp         = (const float*)d_in[8];
    const float* out_proj_w = (const float*)d_in[9];
    const float* norm_w     = (const float*)d_in[10];
    float* out = (float*)d_out;

    float *xz = nullptr, *mid = nullptr, *wT = nullptr, *rs0 = nullptr, *rs1 = nullptr;
    cudaGetSymbolAddress((void**)&xz, g_xz);
    cudaGetSymbolAddress((void**)&mid, g_mid);
    cudaGetSymbolAddress((void**)&wT, g_wT);
    cudaGetSymbolAddress((void**)&rs0, g_rs0);
    cudaGetSymbolAddress((void**)&rs1, g_rs1);

    const int CONV_SMEM  = (144 * 56 + 216 * 68) * 4;                // 91008
    const int FUSED_SMEM = (1848 + 7448 + 96 * 196) * 4;             // 112448
    cudaFuncSetAttribute(conv_kernel,  cudaFuncAttributeMaxDynamicSharedMemorySize, CONV_SMEM);
    cudaFuncSetAttribute(fused_kernel, cudaFuncAttributeMaxDynamicSharedMemorySize, FUSED_SMEM);

    wt_kernel<<<dim3(27, 12, 2), dim3(32, 8)>>>(in_proj_w);

    // layer 0: input = x depth-0 slice (strided view)
    {
        long cs = 8L * NPOS, ns = 96L * 8L * NPOS;
        rs_kernel<<<36, 128>>>(x, cs, ns, norm_w, rs0);
        conv_kernel<<<dim3(6, 6, 8), 192, CONV_SMEM>>>(wT, x, cs, ns, rs0, xz);
        fused_kernel<<<dim3(72, 2), 192, FUSED_SMEM>>>(
            conv1d_w, conv1d_b, x_proj_w, dt_proj_w, dt_proj_b, Dp, out_proj_w,
            x, cs, ns, mid);
    }
    // layer 1: input = mid (contiguous)
    {
        long cs = (long)NPOS, ns = 96L * NPOS;
        rs_kernel<<<36, 128>>>(mid, cs, ns, norm_w + 96, rs1);
        conv_kernel<<<dim3(6, 6, 8), 192, CONV_SMEM>>>(
            wT + 331776, mid, cs, ns, rs1, xz);
        fused_kernel<<<dim3(72, 2), 192, FUSED_SMEM>>>(
            conv1d_w + 768, conv1d_b + 192, x_proj_w + 7296, dt_proj_w + 1152,
            dt_proj_b + 192, Dp + 192, out_proj_w + 18432,
            mid, cs, ns, out);
    }
}

// round 8
// speedup vs baseline: 1.8752x; 1.1303x over previous
#include <cuda_runtime.h>
#include <math.h>

#define HW 24
#define NPOS 576
#define XZQ 442368            // one K-quarter of xz: 2n * 384 * 576

// Scratch (__device__ globals: allocation-free rule)
__device__ float g_xz[4 * XZQ];          // [kq][n][384][576]
__device__ float g_mid[2 * 96 * NPOS];
__device__ float g_wT[2 * 864 * 384];
__device__ float g_rs0[2 * 96 * 24];     // layer-0 rms row scales
__device__ float g_rs1[2 * 96 * 24];     // layer-1 rms row scales

typedef unsigned long long ull;

__device__ __forceinline__ void ffma2(ull& acc, ull a, ull b) {
    asm("fma.rn.f32x2 %0, %1, %2, %0;" : "+l"(acc) : "l"(a), "l"(b));
}
__device__ __forceinline__ float2 up(ull a) { return *(float2*)&a; }

// ---------- weight transpose: [co][ci*9+t] -> [ci*9+t][co] ----------
__global__ void wt_kernel(const float* __restrict__ ipw) {
    __shared__ float tile[32][33];
    int r0 = blockIdx.x * 32, c0 = blockIdx.y * 32, l = blockIdx.z;
    int tx = threadIdx.x, ty = threadIdx.y;   // (32, 8)
    const float* src = ipw + (size_t)l * 331776;
    float* dst = g_wT + (size_t)l * 331776;
    #pragma unroll
    for (int i = 0; i < 4; i++)
        tile[ty + 8 * i][tx] = src[(size_t)(c0 + ty + 8 * i) * 864 + r0 + tx];
    __syncthreads();
    #pragma unroll
    for (int i = 0; i < 4; i++)
        dst[(size_t)(r0 + ty + 8 * i) * 384 + c0 + tx] = tile[tx][ty + 8 * i];
}

// ---------- rms row scales (no data rewrite) ----------
__global__ void rs_kernel(const float* __restrict__ src, long cs, long ns,
                          const float* __restrict__ nw, float* __restrict__ rs) {
    int row = blockIdx.x * 128 + threadIdx.x;
    if (row >= 2 * 96 * 24) return;
    int h = row % 24;
    int c = (row / 24) % 96;
    int n = row / (24 * 96);
    const float* p = src + (size_t)n * ns + (size_t)c * cs + h * 24;
    float s = 0.f;
    #pragma unroll
    for (int j = 0; j < 6; j++) {
        float4 v = *(const float4*)(p + 4 * j);
        s += v.x * v.x + v.y * v.y + v.z * v.z + v.w * v.w;
    }
    rs[(n * 96 + c) * 24 + h] = rsqrtf(s * (1.f / 24.f) + 1e-5f) * __ldg(nw + c);
}

// ---------- 3x3 conv (96 -> 384), scale applied at staging, K-split by 4 ----------
// block: 64 co x (4h x 24w), 24-ci quarter; 192 threads, 2 CTAs/SM
// grid: (6 htile, 6 ctile, 8 = n*4 + kq)
__global__ void __launch_bounds__(192, 2)
conv_kernel(const float* __restrict__ wT,
            const float* __restrict__ src, long cs, long ns,
            const float* __restrict__ rs,
            float* __restrict__ outp) {
    extern __shared__ float sm[];
    float2* S2 = (float2*)sm;          // [144][28] float2, values duplicated
    float*  W  = sm + 144 * 56;        // [216][68]

    int h0  = blockIdx.x * 4;
    int ct  = blockIdx.y;
    int n   = blockIdx.z >> 2;
    int kq  = blockIdx.z & 3;
    int ci0 = kq * 24;
    int tid = threadIdx.x;

    const float* sb = src + (size_t)n * ns + (size_t)ci0 * cs;
    const float* rb = rs + (n * 96 + ci0) * 24;
    for (int idx = tid; idx < 24 * 6 * 24; idx += 192) {
        int w = idx % 24;
        int row = idx / 24;
        int hr = row % 6, ci = row / 6;
        int hh = h0 + hr - 1;
        float v = 0.f;
        if (hh >= 0 && hh < 24)
            v = sb[(size_t)ci * cs + hh * 24 + w] * __ldg(rb + ci * 24 + hh);
        S2[row * 28 + 1 + w] = make_float2(v, v);
    }
    if (tid < 144) {
        float2 z = make_float2(0.f, 0.f);
        S2[tid * 28] = z; S2[tid * 28 + 25] = z;
        S2[tid * 28 + 26] = z; S2[tid * 28 + 27] = z;
    }
    {
        const float* wsrc = wT + (size_t)(ci0 * 9) * 384 + ct * 64;
        for (int idx = tid; idx < 216 * 16; idx += 192) {
            int r = idx >> 4, fq = idx & 15;
            *(float4*)(W + r * 68 + fq * 4) = *(const float4*)(wsrc + (size_t)r * 384 + fq * 4);
        }
    }
    __syncthreads();

    int cog  = tid & 15;
    int posg = tid >> 4;
    int hl   = (posg / 6) * 2;
    int w0   = (posg % 6) * 4;

    ull acc[2][2][4];
    #pragma unroll
    for (int a = 0; a < 2; a++)
        #pragma unroll
        for (int dh = 0; dh < 2; dh++)
            #pragma unroll
            for (int dw = 0; dw < 4; dw++) acc[a][dh][dw] = 0ull;

    const float2* Sbase = S2 + hl * 28 + w0;
    const float*  Wbase = W + cog * 4;

    #pragma unroll 1
    for (int ci = 0; ci < 24; ci++) {
        const float2* Sr = Sbase + ci * 168;
        ull ind[4][6];
        #pragma unroll
        for (int r = 0; r < 4; r++) {
            const float4* rp = (const float4*)(Sr + r * 28);
            float4 t0 = rp[0], t1 = rp[1], t2 = rp[2];
            ind[r][0] = *(ull*)&t0.x; ind[r][1] = *(ull*)&t0.z;
            ind[r][2] = *(ull*)&t1.x; ind[r][3] = *(ull*)&t1.z;
            ind[r][4] = *(ull*)&t2.x; ind[r][5] = *(ull*)&t2.z;
        }

        const float* Wr = Wbase + ci * 9 * 68;
        #pragma unroll
        for (int kh = 0; kh < 3; kh++) {
            #pragma unroll
            for (int kw = 0; kw < 3; kw++) {
                const float4 wv = *(const float4*)(Wr + (kh * 3 + kw) * 68);
                ull w01 = *(const ull*)&wv.x;
                ull w23 = *(const ull*)&wv.z;
                #pragma unroll
                for (int dh = 0; dh < 2; dh++) {
                    #pragma unroll
                    for (int dw = 0; dw < 4; dw++) {
                        ffma2(acc[0][dh][dw], w01, ind[dh + kh][dw + kw]);
                        ffma2(acc[1][dh][dw], w23, ind[dh + kh][dw + kw]);
                    }
                }
            }
        }
    }

    int cobase = ct * 64 + cog * 4;
    float* ob = outp + (size_t)kq * XZQ
              + ((size_t)(n * 384 + cobase)) * NPOS + (h0 + hl) * 24 + w0;
    #pragma unroll
    for (int a = 0; a < 2; a++) {
        #pragma unroll
        for (int dh = 0; dh < 2; dh++) {
            float2 v0 = up(acc[a][dh][0]), v1 = up(acc[a][dh][1]);
            float2 v2 = up(acc[a][dh][2]), v3 = up(acc[a][dh][3]);
            float4 lo = make_float4(v0.x, v1.x, v2.x, v3.x);
            float4 hi = make_float4(v0.y, v1.y, v2.y, v3.y);
            *(float4*)(ob + (size_t)(2 * a) * NPOS + dh * 24)     = lo;
            *(float4*)(ob + (size_t)(2 * a + 1) * NPOS + dh * 24) = hi;
        }
    }
}

// ---------- fused pointwise chain + GEMVs over 8-position tiles ----------
// 384 threads (12 warps), grid (72 ptiles, 2 n). Weights via direct LDG (L2-hot).
__global__ void __launch_bounds__(384, 1)
fused_kernel(const float* __restrict__ cw,  const float* __restrict__ cb,
             const float* __restrict__ xpw, const float* __restrict__ dtw,
             const float* __restrict__ dtb, const float* __restrict__ Dp,
             const float* __restrict__ opw,
             const float* __restrict__ resid, long cs, long ns,
             float* __restrict__ dst) {
    __shared__ float xi_s[192 * 8];
    __shared__ float dbc_s[38 * 8];
    __shared__ float bc_s[8];

    int tid = threadIdx.x;
    int p0 = blockIdx.x * 8;
    int n  = blockIdx.y;
    const float* xzb = g_xz + (size_t)n * 384 * NPOS + p0;

    // phase 1: xi = silu(conv1d depth-0 tap + bias); sum four K-quarters
    for (int idx = tid; idx < 1536; idx += 384) {
        int c = idx >> 3, p = idx & 7;
        size_t o = (size_t)c * NPOS + p;
        float v = xzb[o] + xzb[XZQ + o] + xzb[2 * XZQ + o] + xzb[3 * XZQ + o];
        float pre = __ldg(cw + c * 4 + 3) * v + __ldg(cb + c);
        xi_s[idx] = pre / (1.f + __expf(-pre));
    }
    __syncthreads();

    // phase 2: dbc[38][8] = x_proj @ xi   (thread = (j, pos-pair))
    {
        int j = tid >> 2, pp = tid & 3;
        if (j < 38) {
            float a0 = 0.f, b0 = 0.f, a1 = 0.f, b1 = 0.f;   // 2 c-halves x 2 pos
            const float4* wr = (const float4*)(xpw + (size_t)j * 192);
            const float* xr = xi_s + pp * 2;
            #pragma unroll 6
            for (int c4 = 0; c4 < 24; c4++) {
                float4 w = __ldg(wr + c4);
                float4 w2 = __ldg(wr + 24 + c4);
                #pragma unroll
                for (int u = 0; u < 4; u++) {
                    float wv = (&w.x)[u];
                    float2 x = *(const float2*)(xr + (4 * c4 + u) * 8);
                    a0 += wv * x.x; b0 += wv * x.y;
                    float wv2 = (&w2.x)[u];
                    float2 x2 = *(const float2*)(xr + (96 + 4 * c4 + u) * 8);
                    a1 += wv2 * x2.x; b1 += wv2 * x2.y;
                }
            }
            dbc_s[j * 8 + pp * 2]     = a0 + a1;
            dbc_s[j * 8 + pp * 2 + 1] = b0 + b1;
        }
    }
    __syncthreads();

    // phase 3: bc[p] = B . C
    if (tid < 8) {
        float s = 0.f;
        #pragma unroll
        for (int qq = 0; qq < 16; qq++)
            s += dbc_s[(6 + qq) * 8 + tid] * dbc_s[(22 + qq) * 8 + tid];
        bc_s[tid] = s;
    }
    __syncthreads();

    // phase 4: delta -> y -> gate; overwrite xi_s with g (thread = channel)
    if (tid < 192) {
        int c = tid;
        float dw[6];
        #pragma unroll
        for (int r = 0; r < 6; r++) dw[r] = __ldg(dtw + c * 6 + r);
        float bconst = __ldg(dtb + c);
        float Dc = __ldg(Dp + c);
        const float* zrow = xzb + (size_t)(192 + c) * NPOS;
        float z[8];
        #pragma unroll
        for (int jj = 0; jj < 2; jj++) {
            float4 a = *(const float4*)(zrow + 4 * jj);
            #pragma unroll
            for (int q = 1; q < 4; q++) {
                float4 t = *(const float4*)(zrow + (size_t)q * XZQ + 4 * jj);
                a.x += t.x; a.y += t.y; a.z += t.z; a.w += t.w;
            }
            z[4 * jj] = a.x; z[4 * jj + 1] = a.y; z[4 * jj + 2] = a.z; z[4 * jj + 3] = a.w;
        }
        #pragma unroll
        for (int p = 0; p < 8; p++) {
            float d = bconst;
            #pragma unroll
            for (int r = 0; r < 6; r++) d += dw[r] * dbc_s[r * 8 + p];
            float sp = fmaxf(d, 0.f) + log1pf(__expf(-fabsf(d)));
            float zv = z[p];
            xi_s[c * 8 + p] = xi_s[c * 8 + p] * (sp * bc_s[p] + Dc)
                            * (zv / (1.f + __expf(-zv)));
        }
    }
    __syncthreads();

    // phase 5: out = out_proj @ g + residual (thread = (k, pos-pair), 96x4 = 384)
    {
        int k = tid >> 2, pp = tid & 3;
        float a0 = 0.f, b0 = 0.f, a1 = 0.f, b1 = 0.f;
        const float4* wr = (const float4*)(opw + (size_t)k * 192);
        const float* xr = xi_s + pp * 2;
        #pragma unroll 6
        for (int c4 = 0; c4 < 24; c4++) {
            float4 w = __ldg(wr + c4);
            float4 w2 = __ldg(wr + 24 + c4);
            #pragma unroll
            for (int u = 0; u < 4; u++) {
                float wv = (&w.x)[u];
                float2 x = *(const float2*)(xr + (4 * c4 + u) * 8);
                a0 += wv * x.x; b0 += wv * x.y;
                float wv2 = (&w2.x)[u];
                float2 x2 = *(const float2*)(xr + (96 + 4 * c4 + u) * 8);
                a1 += wv2 * x2.x; b1 += wv2 * x2.y;
            }
        }
        const float* rb = resid + (size_t)n * ns + (size_t)k * cs + p0 + pp * 2;
        float2 v = make_float2(a0 + a1 + rb[0], b0 + b1 + rb[1]);
        *(float2*)(dst + (size_t)(n * 96 + k) * NPOS + p0 + pp * 2) = v;
    }
}

extern "C" void kernel_launch(void* const* d_in, const int* in_sizes, int n_in,
                              void* d_out, int out_size) {
    const float* x          = (const float*)d_in[0];
    const float* in_proj_w  = (const float*)d_in[1];
    const float* conv1d_w   = (const float*)d_in[2];
    const float* conv1d_b   = (const float*)d_in[3];
    const float* x_proj_w   = (const float*)d_in[4];
    const float* dt_proj_w  = (const float*)d_in[5];
    const float* dt_proj_b  = (const float*)d_in[6];
    // d_in[7] = A_log : unused (hs at depth 0 == BX at depth 0)
    const float* Dp         = (const float*)d_in[8];
    const float* out_proj_w = (const float*)d_in[9];
    const float* norm_w     = (const float*)d_in[10];
    float* out = (float*)d_out;

    float *xz = nullptr, *mid = nullptr, *wT = nullptr, *rs0 = nullptr, *rs1 = nullptr;
    cudaGetSymbolAddress((void**)&xz, g_xz);
    cudaGetSymbolAddress((void**)&mid, g_mid);
    cudaGetSymbolAddress((void**)&wT, g_wT);
    cudaGetSymbolAddress((void**)&rs0, g_rs0);
    cudaGetSymbolAddress((void**)&rs1, g_rs1);

    const int CONV_SMEM = (144 * 56 + 216 * 68) * 4;   // 91008
    cudaFuncSetAttribute(conv_kernel, cudaFuncAttributeMaxDynamicSharedMemorySize, CONV_SMEM);

    wt_kernel<<<dim3(27, 12, 2), dim3(32, 8)>>>(in_proj_w);

    // layer 0: input = x depth-0 slice (strided view)
    {
        long cs = 8L * NPOS, ns = 96L * 8L * NPOS;
        rs_kernel<<<36, 128>>>(x, cs, ns, norm_w, rs0);
        conv_kernel<<<dim3(6, 6, 8), 192, CONV_SMEM>>>(wT, x, cs, ns, rs0, xz);
        fused_kernel<<<dim3(72, 2), 384>>>(
            conv1d_w, conv1d_b, x_proj_w, dt_proj_w, dt_proj_b, Dp, out_proj_w,
            x, cs, ns, mid);
    }
    // layer 1: input = mid (contiguous)
    {
        long cs = (long)NPOS, ns = 96L * NPOS;
        rs_kernel<<<36, 128>>>(mid, cs, ns, norm_w + 96, rs1);
        conv_kernel<<<dim3(6, 6, 8), 192, CONV_SMEM>>>(
            wT + 331776, mid, cs, ns, rs1, xz);
        fused_kernel<<<dim3(72, 2), 384>>>(
            conv1d_w + 768, conv1d_b + 192, x_proj_w + 7296, dt_proj_w + 1152,
            dt_proj_b + 192, Dp + 192, out_proj_w + 18432,
            mid, cs, ns, out);
    }
}